// round 1
// baseline (speedup 1.0000x reference)
#include <cuda_runtime.h>
#include <math_constants.h>

#define RR 512
#define CC 768
#define DD 256
#define HH 8
#define HD 32

#define SCALE_F 0.17677669529663687f   /* 1/sqrt(32) */

// Scratch: p[c][h][D] as float4 (768*8*64 float4 = 6.29 MB). Static device array
// (no allocation; permitted by harness rules).
__device__ float4 g_p4[CC * HH * (DD / 4)];

// ---------------------------------------------------------------------------
// Kernel P: compute p[c,h,:] = (SCALE * (MSA[0,0,c,:] @ Wq.T))[h*32..h*32+32) @ Wk[h*32..,:]
// Grid: 96 blocks x 8 columns each, 256 threads.
// ---------------------------------------------------------------------------
__global__ __launch_bounds__(256) void kernelP(const float* __restrict__ msa,
                                               const float* __restrict__ Wq,
                                               const float* __restrict__ Wk) {
    __shared__ float q_s[8 * DD];    // q rows for 8 columns
    __shared__ float qf_s[8 * DD];   // projected+scaled Q for 8 columns

    const int t  = threadIdx.x;      // 0..255
    const int c0 = blockIdx.x * 8;

    // Load 8 query rows: MSA[0,0,c0..c0+8, :] is contiguous (8 KB).
    {
        const float4* src = (const float4*)(msa + (size_t)c0 * DD);
        float4* dst = (float4*)q_s;
        for (int i = t; i < 8 * DD / 4; i += 256) dst[i] = src[i];
    }
    __syncthreads();

    // Phase A: Qf[c][j] = SCALE * dot(q[c], Wq[j]); thread t owns j = t.
    {
        float acc[8];
#pragma unroll
        for (int c = 0; c < 8; c++) acc[c] = 0.f;
        const float4* wq = (const float4*)(Wq + (size_t)t * DD);
        const float4* q4 = (const float4*)q_s;
#pragma unroll 8
        for (int i = 0; i < DD / 4; i++) {
            float4 w = wq[i];
#pragma unroll
            for (int c = 0; c < 8; c++) {
                float4 q = q4[c * (DD / 4) + i];
                acc[c] += w.x * q.x;
                acc[c] += w.y * q.y;
                acc[c] += w.z * q.z;
                acc[c] += w.w * q.w;
            }
        }
#pragma unroll
        for (int c = 0; c < 8; c++) qf_s[c * DD + t] = acc[c] * SCALE_F;
    }
    __syncthreads();

    // Phase B: p[c][h][D] = sum_{d<32} Qf[c][h*32+d] * Wk[h*32+d][D]
    // Thread layout: 64 threads span D (float4 each), 4 groups each own 2 columns.
    {
        const int d4 = t & 63;
        const int cg = t >> 6;
        const int cA = 2 * cg, cB = 2 * cg + 1;
        const float4* wk = (const float4*)Wk;
        for (int h = 0; h < HH; h++) {
            float4 a0 = make_float4(0.f, 0.f, 0.f, 0.f);
            float4 a1 = make_float4(0.f, 0.f, 0.f, 0.f);
#pragma unroll
            for (int d = 0; d < HD; d++) {
                float4 w = wk[(h * HD + d) * (DD / 4) + d4];   // coalesced across lanes
                float f0 = qf_s[cA * DD + h * HD + d];         // warp-uniform -> broadcast
                float f1 = qf_s[cB * DD + h * HD + d];
                a0.x += f0 * w.x; a0.y += f0 * w.y; a0.z += f0 * w.z; a0.w += f0 * w.w;
                a1.x += f1 * w.x; a1.y += f1 * w.y; a1.z += f1 * w.z; a1.w += f1 * w.w;
            }
            g_p4[((size_t)(c0 + cA) * HH + h) * (DD / 4) + d4] = a0;
            g_p4[((size_t)(c0 + cB) * HH + h) * (DD / 4) + d4] = a1;
        }
    }
}

// ---------------------------------------------------------------------------
// Kernel Main: one block per column c. Stream MSA[:, c, :] (512 KB) once,
// compute logits[r][h] = dot(MSA[r,c,:], p[c,h,:]), masked softmax over r,
// write out[r][c][h].
// ---------------------------------------------------------------------------
__global__ __launch_bounds__(256, 2) void kernelMain(const float* __restrict__ msa,
                                                     const int* __restrict__ mask,
                                                     float* __restrict__ out) {
    __shared__ float logit_s[RR * 9];   // [r][h], padded row stride 9 (conflict-free)
    __shared__ int   mask_s[RR];

    const int c    = blockIdx.x;
    const int t    = threadIdx.x;
    const int warp = t >> 5;
    const int lane = t & 31;

    for (int i = t; i < RR; i += 256) mask_s[i] = mask[i];

    // p[c] resident in registers: lane covers D = 4*lane..+3 and 128+4*lane..+3 per head.
    float4 pA[HH], pB[HH];
    {
        const float4* pg = g_p4 + (size_t)c * HH * (DD / 4);
#pragma unroll
        for (int h = 0; h < HH; h++) {
            pA[h] = pg[h * 64 + lane];
            pB[h] = pg[h * 64 + 32 + lane];
        }
    }

    const bool hi16 = (lane & 16) != 0;
    const bool hi8  = (lane & 8) != 0;
    const bool hi4  = (lane & 4) != 0;
    const int  hsel = (lane >> 2) & 7;

    // Main streaming loop: warp w handles r = w, w+8, ..., w+504.
#pragma unroll 2
    for (int i = 0; i < RR / 8; i++) {
        const int r = warp + (i << 3);
        const float4* row = (const float4*)(msa + ((size_t)r * CC + c) * DD);
        float4 mA = row[lane];
        float4 mB = row[32 + lane];

        float acc[HH];
#pragma unroll
        for (int h = 0; h < HH; h++) {
            float s;
            s  = mA.x * pA[h].x;
            s += mA.y * pA[h].y;
            s += mA.z * pA[h].z;
            s += mA.w * pA[h].w;
            s += mB.x * pB[h].x;
            s += mB.y * pB[h].y;
            s += mB.z * pB[h].z;
            s += mB.w * pB[h].w;
            acc[h] = s;
        }

        // Segmented butterfly reduction: 8 partials x 32 lanes -> head totals
        // in 4-lane groups (9 SHFL + 9 FADD instead of 40+40).
        float k1[4];
#pragma unroll
        for (int j = 0; j < 4; j++) {
            float send = hi16 ? acc[j] : acc[j + 4];
            float recv = __shfl_xor_sync(0xffffffffu, send, 16);
            k1[j] = (hi16 ? acc[j + 4] : acc[j]) + recv;
        }
        float k2[2];
#pragma unroll
        for (int j = 0; j < 2; j++) {
            float send = hi8 ? k1[j] : k1[j + 2];
            float recv = __shfl_xor_sync(0xffffffffu, send, 8);
            k2[j] = (hi8 ? k1[j + 2] : k1[j]) + recv;
        }
        {
            float send = hi4 ? k2[0] : k2[1];
            float recv = __shfl_xor_sync(0xffffffffu, send, 4);
            float res  = (hi4 ? k2[1] : k2[0]) + recv;
            res += __shfl_xor_sync(0xffffffffu, res, 2);
            res += __shfl_xor_sync(0xffffffffu, res, 1);
            if ((lane & 3) == 0) logit_s[r * 9 + hsel] = res;
        }
    }
    __syncthreads();

    // Masked softmax over r: warp w owns head h = w (8 warps, 8 heads).
    {
        const int h = warp;
        float vals[16];
        float mx = -CUDART_INF_F;
#pragma unroll
        for (int i = 0; i < 16; i++) {
            const int r = i * 32 + lane;
            float v = logit_s[r * 9 + h];
            vals[i] = v;
            if (mask_s[r] != 0) mx = fmaxf(mx, v);
        }
#pragma unroll
        for (int o = 16; o > 0; o >>= 1)
            mx = fmaxf(mx, __shfl_xor_sync(0xffffffffu, mx, o));

        if (mx > -CUDART_INF_F) {
            float sum = 0.f;
#pragma unroll
            for (int i = 0; i < 16; i++) {
                const int r = i * 32 + lane;
                float e = (mask_s[r] != 0) ? __expf(vals[i] - mx) : 0.f;
                vals[i] = e;
                sum += e;
            }
#pragma unroll
            for (int o = 16; o > 0; o >>= 1)
                sum += __shfl_xor_sync(0xffffffffu, sum, o);
            const float inv = 1.f / sum;
#pragma unroll
            for (int i = 0; i < 16; i++) {
                const int r = i * 32 + lane;
                logit_s[r * 9 + h] = vals[i] * inv;
            }
        } else {
            // all rows masked: reference gives uniform softmax of equal finfo.min
            const float u = 1.0f / (float)RR;
#pragma unroll
            for (int i = 0; i < 16; i++) {
                const int r = i * 32 + lane;
                logit_s[r * 9 + h] = u;
            }
        }
    }
    __syncthreads();

    // Output: out[((r*CC + c)*HH) + h]. Groups of 8 lanes write 32B contiguous
    // sectors (h contiguous), full sector utilization at DRAM.
    {
        const int h  = t & 7;
        const int r0 = t >> 3;   // 0..31
#pragma unroll
        for (int i = 0; i < 16; i++) {
            const int r = i * 32 + r0;
            out[((size_t)r * CC + c) * HH + h] = logit_s[r * 9 + h];
        }
    }
}

// ---------------------------------------------------------------------------
extern "C" void kernel_launch(void* const* d_in, const int* in_sizes, int n_in,
                              void* d_out, int out_size) {
    const float* msa  = (const float*)d_in[0];   // MSA_emb (1,512,768,256) f32
    const int*   mask = (const int*)d_in[1];     // seq_mask (1,512) i32
    const float* Wq   = (const float*)d_in[2];   // (256,256) f32
    const float* Wk   = (const float*)d_in[3];   // (256,256) f32
    float* out = (float*)d_out;                  // (1,512,768,8,1) f32

    kernelP<<<CC / 8, 256>>>(msa, Wq, Wk);
    kernelMain<<<CC, 256>>>(msa, mask, out);
}